// round 8
// baseline (speedup 1.0000x reference)
#include <cuda_runtime.h>
#include <cuda_bf16.h>
#include <cstdint>

#define BB 256
#define NTOK 63
#define DD 128
#define EE 8
#define HH 256
#define T2 160
#define OUTN (BB * NTOK * T2)

// ---------------- device globals ----------------
__device__ float g_gates[BB * 2];
__device__ int   g_eidx[BB * 2];
__device__ __nv_bfloat16 W1Th[EE * HH * DD];     // [e][hcol][d] k-contig
__device__ __nv_bfloat16 W1Tl[EE * HH * DD];
__device__ __nv_bfloat16 W2Th[EE * 4 * T2 * 64]; // [e][kchunk][o][64]
__device__ __nv_bfloat16 W2Tl[EE * 4 * T2 * 64];

// ---------------- smem layout (bytes) ----------------
#define SM_XH  0        // x hi: 64 rows x 256B (swz)
#define SM_XL  16384
#define SM_HH  32768    // h chunk hi: 64 rows x 128B (swz)
#define SM_HL  40960
#define SM_B1H 49152    // W1 chunk hi: 64 rows x 256B (swz)
#define SM_B1L 65536
#define SM_B2  81920    // 3 rotating k16 buffers: hi 5120 + lo 5120 each
#define B2SZ   10240
#define SM_BIAS (SM_B2 + 3 * B2SZ)   // 112640, 160 floats
#define SM_TOT  (SM_BIAS + 1024)     // 113664

// ---------------- PTX helpers ----------------
__device__ __forceinline__ uint32_t smem_u32(const void* p) {
    uint32_t a;
    asm("{ .reg .u64 t; cvta.to.shared.u64 t, %1; cvt.u32.u64 %0, t; }" : "=r"(a) : "l"(p));
    return a;
}
__device__ __forceinline__ void ldsm4(uint32_t* r, uint32_t addr) {
    asm volatile("ldmatrix.sync.aligned.m8n8.x4.shared.b16 {%0,%1,%2,%3}, [%4];"
        : "=r"(r[0]), "=r"(r[1]), "=r"(r[2]), "=r"(r[3]) : "r"(addr));
}
__device__ __forceinline__ void mma16(float* d, const uint32_t* a, uint32_t b0, uint32_t b1) {
    asm volatile("mma.sync.aligned.m16n8k16.row.col.f32.bf16.bf16.f32 "
        "{%0,%1,%2,%3}, {%4,%5,%6,%7}, {%8,%9}, {%0,%1,%2,%3};"
        : "+f"(d[0]), "+f"(d[1]), "+f"(d[2]), "+f"(d[3])
        : "r"(a[0]), "r"(a[1]), "r"(a[2]), "r"(a[3]), "r"(b0), "r"(b1));
}
__device__ __forceinline__ void cp16(uint32_t dst, const void* src) {
    asm volatile("cp.async.cg.shared.global [%0], [%1], 16;" :: "r"(dst), "l"(src));
}
#define CP_COMMIT() asm volatile("cp.async.commit_group;" ::: "memory")
#define CP_WAIT(n)  asm volatile("cp.async.wait_group %0;" :: "n"(n) : "memory")

// ---------------- prep (fused): transpose + bf16 hi/lo split + out zero ----------------
__global__ void prep_w(const float* __restrict__ w1, const float* __restrict__ w2,
                       float* __restrict__ out) {
    __shared__ float t[32][33];
    int e = blockIdx.z, bx = blockIdx.x;
    int tx = threadIdx.x, ty = threadIdx.y;

    // grid-stride zero of out (poisoned by harness)
    {
        int gtid = (blockIdx.z * gridDim.x + blockIdx.x) * 256 + ty * 32 + tx;
        float4* o4 = (float4*)out;
        for (int i = gtid; i < OUTN / 4; i += 576 * 256)
            o4[i] = make_float4(0.f, 0.f, 0.f, 0.f);
    }

    if (bx < 32) {
        int d0 = (bx & 3) * 32, h0 = (bx >> 2) * 32;
        #pragma unroll
        for (int i = 0; i < 4; i++)
            t[ty + 8 * i][tx] = w1[(e * DD + d0 + ty + 8 * i) * HH + h0 + tx];
        __syncthreads();
        #pragma unroll
        for (int i = 0; i < 4; i++) {
            float v = t[tx][ty + 8 * i];
            int idx = (e * HH + h0 + ty + 8 * i) * DD + d0 + tx;
            __nv_bfloat16 h = __float2bfloat16(v);
            W1Th[idx] = h;
            W1Tl[idx] = __float2bfloat16(v - __bfloat162float(h));
        }
    } else {
        int i2 = bx - 32;
        int k0 = (i2 & 7) * 32, o0 = (i2 >> 3) * 32;
        #pragma unroll
        for (int i = 0; i < 4; i++)
            t[ty + 8 * i][tx] = w2[(e * HH + k0 + ty + 8 * i) * T2 + o0 + tx];
        __syncthreads();
        #pragma unroll
        for (int i = 0; i < 4; i++) {
            int hd = k0 + tx, o = o0 + ty + 8 * i;
            float v = t[tx][ty + 8 * i];
            int idx = ((e * 4 + (hd >> 6)) * T2 + o) * 64 + (hd & 63);
            __nv_bfloat16 h = __float2bfloat16(v);
            W2Th[idx] = h;
            W2Tl[idx] = __float2bfloat16(v - __bfloat162float(h));
        }
    }
}

// ---------------- router ----------------
__global__ void router_kernel(const float* __restrict__ x,
                              const float* __restrict__ rw,
                              const float* __restrict__ rb) {
    int b = blockIdx.x;
    __shared__ float pooled[DD];
    __shared__ float logits[EE];
    int d = threadIdx.x;
    const float* xb = x + b * 64 * DD;
    float s = 0.f;
    #pragma unroll 4
    for (int n = 1; n < 64; n++) s += xb[n * DD + d];
    pooled[d] = s * (1.0f / 63.0f);
    __syncthreads();
    if (d < EE) {
        float l = rb[d];
        #pragma unroll 4
        for (int dd = 0; dd < DD; dd++) l += pooled[dd] * rw[dd * EE + d];
        logits[d] = l;
    }
    __syncthreads();
    if (d == 0) {
        float mx = logits[0];
        #pragma unroll
        for (int e = 1; e < EE; e++) mx = fmaxf(mx, logits[e]);
        float p[EE];
        float se = 0.f;
        #pragma unroll
        for (int e = 0; e < EE; e++) { p[e] = expf(logits[e] - mx); se += p[e]; }
        int i1 = 0;
        #pragma unroll
        for (int e = 1; e < EE; e++) if (p[e] > p[i1]) i1 = e;
        int i2 = (i1 == 0) ? 1 : 0;
        #pragma unroll
        for (int e = 0; e < EE; e++) if (e != i1 && p[e] > p[i2]) i2 = e;
        float inv = 1.f / se;
        g_eidx[b * 2 + 0]  = i1;
        g_gates[b * 2 + 0] = p[i1] * inv;
        g_eidx[b * 2 + 1]  = i2;
        g_gates[b * 2 + 1] = p[i2] * inv;
    }
}

// ---------------- cp.async tile loaders (guards make over-range calls empty) ----------------
__device__ __forceinline__ void load_b1t(uint32_t sb, int ch, int e, int tid) {
    if (ch >= 4) return;
    const char* sh = (const char*)(W1Th + (e * HH + ch * 64) * DD);
    const char* sl = (const char*)(W1Tl + (e * HH + ch * 64) * DD);
    #pragma unroll
    for (int i = 0; i < 4; i++) {
        int c = tid + i * 256;
        int row = c >> 4, seg = c & 15;
        uint32_t d = (uint32_t)row * 256 + (uint32_t)((seg ^ (row & 7)) << 4);
        cp16(sb + SM_B1H + d, sh + c * 16);
        cp16(sb + SM_B1L + d, sl + c * 16);
    }
}
// gsub = ch*4 + k16sub, buffer = gsub % 3, unpadded 32B rows
__device__ __forceinline__ void load_b2t(uint32_t sb, int gsub, int e, int tid) {
    if (gsub >= 16) return;
    int ch = gsub >> 2, sub = gsub & 3;
    uint32_t buf = sb + SM_B2 + (uint32_t)(gsub % 3) * B2SZ;
    const char* sh = (const char*)(W2Th + (e * 4 + ch) * T2 * 64) + sub * 32;
    const char* sl = (const char*)(W2Tl + (e * 4 + ch) * T2 * 64) + sub * 32;
    #pragma unroll
    for (int i = 0; i < 2; i++) {
        int c = tid + i * 256;
        if (c < 320) {
            int row = c >> 1, seg = (c & 1) * 16;
            uint32_t d = buf + (uint32_t)row * 32 + (uint32_t)seg;
            cp16(d, sh + row * 128 + seg);
            cp16(d + 5120, sl + row * 128 + seg);
        }
    }
}

// ---------------- main kernel: one CTA per (batch, expert-slot) ----------------
__global__ __launch_bounds__(256, 2) void moe_kernel(
    const float* __restrict__ x,
    const float* __restrict__ b1g,
    const float* __restrict__ b2g,
    float* __restrict__ out) {
    extern __shared__ char smem[];
    uint32_t sb = smem_u32(smem);
    int tid = threadIdx.x, wid = tid >> 5, lane = tid & 31;
    const int b = blockIdx.x >> 1, slot = blockIdx.x & 1;
    const int wm = wid & 3, wn = wid >> 2;
    const int t = lane >> 3, r8 = lane & 7, q = lane >> 2, p2 = (lane & 3) * 2;

    const int   e = g_eidx[b * 2 + slot];
    const float g = g_gates[b * 2 + slot];

    // this slot's share of the output bias: g * b2[e]
    if (tid < T2)
        ((float*)(smem + SM_BIAS))[tid] = g * __ldg(b2g + e * T2 + tid);

    if (tid < 16) {
        uint32_t off = 63u * 256 + (uint32_t)((tid ^ 7) << 4);
        *(uint4*)(smem + SM_XH + off) = make_uint4(0, 0, 0, 0);
        *(uint4*)(smem + SM_XL + off) = make_uint4(0, 0, 0, 0);
    }
    if (tid < 252) {
        int r = tid >> 2, seg32 = (tid & 3) * 32;
        const float4* xr = (const float4*)(x + (b * 64 + 1 + r) * DD + seg32);
        #pragma unroll
        for (int j = 0; j < 8; j++) {
            float4 v = xr[j];
            int d = seg32 + j * 4;
            __nv_bfloat16 h0 = __float2bfloat16(v.x), h1 = __float2bfloat16(v.y);
            __nv_bfloat16 h2 = __float2bfloat16(v.z), h3 = __float2bfloat16(v.w);
            __nv_bfloat16 l0 = __float2bfloat16(v.x - __bfloat162float(h0));
            __nv_bfloat16 l1 = __float2bfloat16(v.y - __bfloat162float(h1));
            __nv_bfloat16 l2 = __float2bfloat16(v.z - __bfloat162float(h2));
            __nv_bfloat16 l3 = __float2bfloat16(v.w - __bfloat162float(h3));
            uint32_t off = (uint32_t)r * 256 + (uint32_t)((((d >> 3) ^ (r & 7)) << 4) + ((d * 2) & 15));
            *(__nv_bfloat162*)(smem + SM_XH + off)     = __halves2bfloat162(h0, h1);
            *(__nv_bfloat162*)(smem + SM_XH + off + 4) = __halves2bfloat162(h2, h3);
            *(__nv_bfloat162*)(smem + SM_XL + off)     = __halves2bfloat162(l0, l1);
            *(__nv_bfloat162*)(smem + SM_XL + off + 4) = __halves2bfloat162(l2, l3);
        }
    }
    __syncthreads();

    // prologue groups: [B1(0)] [S0] [S1]
    load_b1t(sb, 0, e, tid);  CP_COMMIT();
    load_b2t(sb, 0, e, tid);  CP_COMMIT();
    load_b2t(sb, 1, e, tid);  CP_COMMIT();

    const int rA = wm * 16 + (t & 1) * 8 + r8;
    const uint32_t xbase = sb + SM_XH + (uint32_t)rA * 256;
    const uint32_t hbase = sb + SM_HH + (uint32_t)rA * 128;
    const int axor = rA & 7;
    const int rB0 = wn * 32 + (t >> 1) * 8 + r8;
    const int rW0 = wn * 80 + (t >> 1) * 8 + r8;

    float acc2[10][4];
    #pragma unroll
    for (int nt = 0; nt < 10; nt++)
        #pragma unroll
        for (int j = 0; j < 4; j++) acc2[nt][j] = 0.f;

    for (int ch = 0; ch < 4; ch++) {
        const int gs = ch * 4;

        // ---- GEMM1: pending [B1(ch),S(gs),S(gs+1)] -> retire B1 ----
        CP_WAIT(2);
        __syncthreads();
        load_b2t(sb, gs + 2, e, tid); CP_COMMIT();

        float acc1[4][4];
        #pragma unroll
        for (int nt = 0; nt < 4; nt++)
            #pragma unroll
            for (int j = 0; j < 4; j++) acc1[nt][j] = 0.f;

        #pragma unroll
        for (int ks = 0; ks < 8; ks++) {
            uint32_t ah[4], al[4];
            uint32_t sa = (uint32_t)(((2 * ks + (t >> 1)) ^ axor) << 4);
            ldsm4(ah, xbase + sa);
            ldsm4(al, xbase + 16384 + sa);
            #pragma unroll
            for (int ntp = 0; ntp < 2; ntp++) {
                int rB = rB0 + ntp * 16;
                uint32_t a = sb + SM_B1H + (uint32_t)rB * 256 +
                             (uint32_t)(((2 * ks + (t & 1)) ^ (rB & 7)) << 4);
                uint32_t bh[4], bl[4];
                ldsm4(bh, a);
                ldsm4(bl, a + 16384);
                mma16(acc1[ntp * 2],     ah, bh[0], bh[1]);
                mma16(acc1[ntp * 2],     al, bh[0], bh[1]);
                mma16(acc1[ntp * 2],     ah, bl[0], bl[1]);
                mma16(acc1[ntp * 2 + 1], ah, bh[2], bh[3]);
                mma16(acc1[ntp * 2 + 1], al, bh[2], bh[3]);
                mma16(acc1[ntp * 2 + 1], ah, bl[2], bl[3]);
            }
        }
        // h epilogue: bias + relu + gate -> bf16 hi/lo (swizzled)
        #pragma unroll
        for (int nt = 0; nt < 4; nt++) {
            int col = wn * 32 + nt * 8 + p2;
            float bv0 = __ldg(b1g + e * HH + ch * 64 + col);
            float bv1 = __ldg(b1g + e * HH + ch * 64 + col + 1);
            int r0 = wm * 16 + q, r1 = r0 + 8;
            float v00 = g * fmaxf(acc1[nt][0] + bv0, 0.f);
            float v01 = g * fmaxf(acc1[nt][1] + bv1, 0.f);
            float v10 = g * fmaxf(acc1[nt][2] + bv0, 0.f);
            float v11 = g * fmaxf(acc1[nt][3] + bv1, 0.f);
            __nv_bfloat16 a0 = __float2bfloat16(v00), a1 = __float2bfloat16(v01);
            __nv_bfloat16 c0 = __float2bfloat16(v10), c1 = __float2bfloat16(v11);
            uint32_t o0 = (uint32_t)r0 * 128 + (uint32_t)((((col >> 3) ^ (r0 & 7)) << 4) + ((col * 2) & 15));
            uint32_t o1 = (uint32_t)r1 * 128 + (uint32_t)((((col >> 3) ^ (r1 & 7)) << 4) + ((col * 2) & 15));
            *(__nv_bfloat162*)(smem + SM_HH + o0) = __halves2bfloat162(a0, a1);
            *(__nv_bfloat162*)(smem + SM_HH + o1) = __halves2bfloat162(c0, c1);
            *(__nv_bfloat162*)(smem + SM_HL + o0) = __halves2bfloat162(
                __float2bfloat16(v00 - __bfloat162float(a0)),
                __float2bfloat16(v01 - __bfloat162float(a1)));
            *(__nv_bfloat162*)(smem + SM_HL + o1) = __halves2bfloat162(
                __float2bfloat16(v10 - __bfloat162float(c0)),
                __float2bfloat16(v11 - __bfloat162float(c1)));
        }

        // ---- GEMM2: 4 k16 subs, rotating buffers, 1 barrier each ----
        #pragma unroll
        for (int kt = 0; kt < 4; kt++) {
            if (kt == 1) { CP_WAIT(1); } else { CP_WAIT(2); }
            __syncthreads();
            if (kt == 1) {
                load_b2t(sb, gs + 3, e, tid); CP_COMMIT();
                load_b1t(sb, ch + 1, e, tid); CP_COMMIT();
            } else if (kt == 2) {
                load_b2t(sb, gs + 4, e, tid); CP_COMMIT();
            } else if (kt == 3) {
                load_b2t(sb, gs + 5, e, tid); CP_COMMIT();
            }
            uint32_t bufb = sb + SM_B2 + (uint32_t)((gs + kt) % 3) * B2SZ;
            uint32_t hah[4], hal[4];
            uint32_t sa = (uint32_t)(((kt * 2 + (t >> 1)) ^ axor) << 4);
            ldsm4(hah, hbase + sa);
            ldsm4(hal, hbase + 8192 + sa);
            #pragma unroll
            for (int ntp = 0; ntp < 5; ntp++) {
                int rW = rW0 + ntp * 16;
                uint32_t a = bufb + (uint32_t)rW * 32 + (uint32_t)((t & 1) << 4);
                uint32_t bh[4], bl[4];
                ldsm4(bh, a);
                ldsm4(bl, a + 5120);
                mma16(acc2[ntp * 2],     hah, bh[0], bh[1]);
                mma16(acc2[ntp * 2],     hal, bh[0], bh[1]);
                mma16(acc2[ntp * 2],     hah, bl[0], bl[1]);
                mma16(acc2[ntp * 2 + 1], hah, bh[2], bh[3]);
                mma16(acc2[ntp * 2 + 1], hal, bh[2], bh[3]);
                mma16(acc2[ntp * 2 + 1], hah, bl[2], bl[3]);
            }
        }
    }

    // ---- final epilogue: slot bias + RED-accumulate into zeroed out ----
    const float* bc = (const float*)(smem + SM_BIAS);
    int r0 = wm * 16 + q;
    #pragma unroll
    for (int nt = 0; nt < 10; nt++) {
        int col = wn * 80 + nt * 8 + p2;
        float bv0 = bc[col], bv1 = bc[col + 1];
        if (r0 < NTOK) {
            float* p = out + (b * NTOK + r0) * T2 + col;
            atomicAdd(p,     acc2[nt][0] + bv0);
            atomicAdd(p + 1, acc2[nt][1] + bv1);
        }
        if (r0 + 8 < NTOK) {
            float* p = out + (b * NTOK + r0 + 8) * T2 + col;
            atomicAdd(p,     acc2[nt][2] + bv0);
            atomicAdd(p + 1, acc2[nt][3] + bv1);
        }
    }
}

extern "C" void kernel_launch(void* const* d_in, const int* in_sizes, int n_in,
                              void* d_out, int out_size) {
    const float* x  = (const float*)d_in[0];
    const float* rw = (const float*)d_in[1];
    const float* rb = (const float*)d_in[2];
    const float* w1 = (const float*)d_in[3];
    const float* b1 = (const float*)d_in[4];
    const float* w2 = (const float*)d_in[5];
    const float* b2 = (const float*)d_in[6];
    float* out = (float*)d_out;

    prep_w<<<dim3(72, 1, EE), dim3(32, 8)>>>(w1, w2, out);
    router_kernel<<<BB, 128>>>(x, rw, rb);

    cudaFuncSetAttribute(moe_kernel, cudaFuncAttributeMaxDynamicSharedMemorySize, SM_TOT);
    moe_kernel<<<BB * 2, 256, SM_TOT>>>(x, b1, b2, out);
}

// round 10
// speedup vs baseline: 1.6882x; 1.6882x over previous
#include <cuda_runtime.h>
#include <cuda_fp16.h>
#include <cstdint>

#define BB 256
#define NTOK 63
#define DD 128
#define EE 8
#define HH 256
#define T2 160

// ---------------- device globals ----------------
__device__ float g_gates[BB * 2];
__device__ int   g_eidx[BB * 2];
__device__ __half W1T[EE * HH * DD];     // [e][hcol][d] k-contig, fp16
__device__ __half W2T[EE * 4 * T2 * 64]; // [e][kchunk][o][64], fp16

// ---------------- smem layout (bytes) ----------------
#define SM_X   0        // x: 64 rows x 256B (swz)
#define SM_H   16384    // h chunk: 64 rows x 128B (swz)
#define SM_B1  24576    // W1 chunk: 64 rows x 256B (swz)
#define SM_B2  40960    // 3 rotating k16 buffers: 5120 each
#define B2SZ   5120
#define SM_BIAS (SM_B2 + 3 * B2SZ)   // 56320, 160 floats
#define SM_TOT  (SM_BIAS + 1024)     // 57344

// ---------------- PTX helpers ----------------
__device__ __forceinline__ uint32_t smem_u32(const void* p) {
    uint32_t a;
    asm("{ .reg .u64 t; cvta.to.shared.u64 t, %1; cvt.u32.u64 %0, t; }" : "=r"(a) : "l"(p));
    return a;
}
__device__ __forceinline__ void ldsm4(uint32_t* r, uint32_t addr) {
    asm volatile("ldmatrix.sync.aligned.m8n8.x4.shared.b16 {%0,%1,%2,%3}, [%4];"
        : "=r"(r[0]), "=r"(r[1]), "=r"(r[2]), "=r"(r[3]) : "r"(addr));
}
__device__ __forceinline__ void mma16(float* d, const uint32_t* a, uint32_t b0, uint32_t b1) {
    asm volatile("mma.sync.aligned.m16n8k16.row.col.f32.f16.f16.f32 "
        "{%0,%1,%2,%3}, {%4,%5,%6,%7}, {%8,%9}, {%0,%1,%2,%3};"
        : "+f"(d[0]), "+f"(d[1]), "+f"(d[2]), "+f"(d[3])
        : "r"(a[0]), "r"(a[1]), "r"(a[2]), "r"(a[3]), "r"(b0), "r"(b1));
}
__device__ __forceinline__ void cp16(uint32_t dst, const void* src) {
    asm volatile("cp.async.cg.shared.global [%0], [%1], 16;" :: "r"(dst), "l"(src));
}
#define CP_COMMIT() asm volatile("cp.async.commit_group;" ::: "memory")
#define CP_WAIT(n)  asm volatile("cp.async.wait_group %0;" :: "n"(n) : "memory")

// ---------------- prep: transpose + fp16 convert ----------------
__global__ void prep_w(const float* __restrict__ w1, const float* __restrict__ w2) {
    __shared__ float t[32][33];
    int e = blockIdx.z, bx = blockIdx.x;
    int tx = threadIdx.x, ty = threadIdx.y;
    if (bx < 32) {
        int d0 = (bx & 3) * 32, h0 = (bx >> 2) * 32;
        #pragma unroll
        for (int i = 0; i < 4; i++)
            t[ty + 8 * i][tx] = w1[(e * DD + d0 + ty + 8 * i) * HH + h0 + tx];
        __syncthreads();
        #pragma unroll
        for (int i = 0; i < 4; i++)
            W1T[(e * HH + h0 + ty + 8 * i) * DD + d0 + tx] =
                __float2half_rn(t[tx][ty + 8 * i]);
    } else {
        int i2 = bx - 32;
        int k0 = (i2 & 7) * 32, o0 = (i2 >> 3) * 32;
        #pragma unroll
        for (int i = 0; i < 4; i++)
            t[ty + 8 * i][tx] = w2[(e * HH + k0 + ty + 8 * i) * T2 + o0 + tx];
        __syncthreads();
        #pragma unroll
        for (int i = 0; i < 4; i++) {
            int hd = k0 + tx, o = o0 + ty + 8 * i;
            W2T[((e * 4 + (hd >> 6)) * T2 + o) * 64 + (hd & 63)] =
                __float2half_rn(t[tx][ty + 8 * i]);
        }
    }
}

// ---------------- router ----------------
__global__ void router_kernel(const float* __restrict__ x,
                              const float* __restrict__ rw,
                              const float* __restrict__ rb) {
    int b = blockIdx.x;
    __shared__ float pooled[DD];
    __shared__ float logits[EE];
    int d = threadIdx.x;
    const float* xb = x + b * 64 * DD;
    float s = 0.f;
    #pragma unroll 4
    for (int n = 1; n < 64; n++) s += xb[n * DD + d];
    pooled[d] = s * (1.0f / 63.0f);
    __syncthreads();
    if (d < EE) {
        float l = rb[d];
        #pragma unroll 4
        for (int dd = 0; dd < DD; dd++) l += pooled[dd] * rw[dd * EE + d];
        logits[d] = l;
    }
    __syncthreads();
    if (d == 0) {
        float mx = logits[0];
        #pragma unroll
        for (int e = 1; e < EE; e++) mx = fmaxf(mx, logits[e]);
        float p[EE];
        float se = 0.f;
        #pragma unroll
        for (int e = 0; e < EE; e++) { p[e] = expf(logits[e] - mx); se += p[e]; }
        int i1 = 0;
        #pragma unroll
        for (int e = 1; e < EE; e++) if (p[e] > p[i1]) i1 = e;
        int i2 = (i1 == 0) ? 1 : 0;
        #pragma unroll
        for (int e = 0; e < EE; e++) if (e != i1 && p[e] > p[i2]) i2 = e;
        float inv = 1.f / se;
        g_eidx[b * 2 + 0]  = i1;
        g_gates[b * 2 + 0] = p[i1] * inv;
        g_eidx[b * 2 + 1]  = i2;
        g_gates[b * 2 + 1] = p[i2] * inv;
    }
}

// ---------------- cp.async tile loaders (over-range calls are empty) ----------------
__device__ __forceinline__ void load_b1t(uint32_t sb, int ch, int e0, int e1, int tid) {
    if (ch >= 8) return;
    int e = (ch >> 2) ? e1 : e0;
    const char* s = (const char*)(W1T + (e * HH + (ch & 3) * 64) * DD);
    #pragma unroll
    for (int i = 0; i < 4; i++) {
        int c = tid + i * 256;
        int row = c >> 4, seg = c & 15;
        uint32_t d = (uint32_t)row * 256 + (uint32_t)((seg ^ (row & 7)) << 4);
        cp16(sb + SM_B1 + d, s + c * 16);
    }
}
// gsub = ch*4 + k16sub, buffer = gsub % 3, unpadded 32B rows (160 rows x 2 segs = 320 copies)
__device__ __forceinline__ void load_b2t(uint32_t sb, int gsub, int e0, int e1, int tid) {
    if (gsub >= 32) return;
    int ch = gsub >> 2, sub = gsub & 3;
    int e = (ch >> 2) ? e1 : e0;
    uint32_t buf = sb + SM_B2 + (uint32_t)(gsub % 3) * B2SZ;
    const char* s = (const char*)(W2T + (e * 4 + (ch & 3)) * T2 * 64) + sub * 32;
    #pragma unroll
    for (int i = 0; i < 2; i++) {
        int c = tid + i * 256;
        if (c < 320) {
            int row = c >> 1, seg = (c & 1) * 16;
            cp16(buf + (uint32_t)row * 32 + (uint32_t)seg, s + row * 128 + seg);
        }
    }
}

// ---------------- main fused kernel ----------------
__global__ __launch_bounds__(256, 2) void moe_kernel(
    const float* __restrict__ x,
    const float* __restrict__ b1g,
    const float* __restrict__ b2g,
    float* __restrict__ out) {
    extern __shared__ char smem[];
    uint32_t sb = smem_u32(smem);
    int tid = threadIdx.x, wid = tid >> 5, lane = tid & 31;
    int b = blockIdx.x;
    const int wm = wid & 3, wn = wid >> 2;
    const int t = lane >> 3, r8 = lane & 7, q = lane >> 2, p2 = (lane & 3) * 2;

    const int e0 = g_eidx[b * 2 + 0], e1 = g_eidx[b * 2 + 1];
    const float gt0 = g_gates[b * 2 + 0], gt1 = g_gates[b * 2 + 1];

    if (tid < T2)
        ((float*)(smem + SM_BIAS))[tid] =
            gt0 * __ldg(b2g + e0 * T2 + tid) + gt1 * __ldg(b2g + e1 * T2 + tid);

    // zero x row 63
    if (tid < 16) {
        uint32_t off = 63u * 256 + (uint32_t)((tid ^ 7) << 4);
        *(uint4*)(smem + SM_X + off) = make_uint4(0, 0, 0, 0);
    }
    // fill x rows 0..62, fp16, swizzled
    if (tid < 252) {
        int r = tid >> 2, seg32 = (tid & 3) * 32;
        const float4* xr = (const float4*)(x + (b * 64 + 1 + r) * DD + seg32);
        #pragma unroll
        for (int j = 0; j < 8; j++) {
            float4 v = xr[j];
            int d = seg32 + j * 4;
            __half2 h01 = __floats2half2_rn(v.x, v.y);
            __half2 h23 = __floats2half2_rn(v.z, v.w);
            uint32_t off = (uint32_t)r * 256 + (uint32_t)((((d >> 3) ^ (r & 7)) << 4) + ((d * 2) & 15));
            *(__half2*)(smem + SM_X + off)     = h01;
            *(__half2*)(smem + SM_X + off + 4) = h23;
        }
    }
    __syncthreads();

    // prologue groups: [B1(0)] [S0] [S1]
    load_b1t(sb, 0, e0, e1, tid);  CP_COMMIT();
    load_b2t(sb, 0, e0, e1, tid);  CP_COMMIT();
    load_b2t(sb, 1, e0, e1, tid);  CP_COMMIT();

    const int rA = wm * 16 + (t & 1) * 8 + r8;
    const uint32_t xbase = sb + SM_X + (uint32_t)rA * 256;
    const uint32_t hbase = sb + SM_H + (uint32_t)rA * 128;
    const int axor = rA & 7;
    const int rB0 = wn * 32 + (t >> 1) * 8 + r8;
    const int rW0 = wn * 80 + (t >> 1) * 8 + r8;

    float acc2[10][4];
    #pragma unroll
    for (int nt = 0; nt < 10; nt++)
        #pragma unroll
        for (int j = 0; j < 4; j++) acc2[nt][j] = 0.f;

    for (int ch = 0; ch < 8; ch++) {
        const int   e  = (ch >> 2) ? e1 : e0;
        const float g  = (ch >> 2) ? gt1 : gt0;
        const int   c4 = ch & 3;
        const int   gs = ch * 4;

        // ---- GEMM1: pending [B1(ch),S(gs),S(gs+1)] -> retire B1 ----
        CP_WAIT(2);
        __syncthreads();
        load_b2t(sb, gs + 2, e0, e1, tid); CP_COMMIT();

        float acc1[4][4];
        #pragma unroll
        for (int nt = 0; nt < 4; nt++)
            #pragma unroll
            for (int j = 0; j < 4; j++) acc1[nt][j] = 0.f;

        #pragma unroll
        for (int ks = 0; ks < 8; ks++) {
            uint32_t ah[4];
            uint32_t sa = (uint32_t)(((2 * ks + (t >> 1)) ^ axor) << 4);
            ldsm4(ah, xbase + sa);
            #pragma unroll
            for (int ntp = 0; ntp < 2; ntp++) {
                int rB = rB0 + ntp * 16;
                uint32_t a = sb + SM_B1 + (uint32_t)rB * 256 +
                             (uint32_t)(((2 * ks + (t & 1)) ^ (rB & 7)) << 4);
                uint32_t bh[4];
                ldsm4(bh, a);
                mma16(acc1[ntp * 2],     ah, bh[0], bh[1]);
                mma16(acc1[ntp * 2 + 1], ah, bh[2], bh[3]);
            }
        }
        // h epilogue: bias + relu + gate -> fp16 (swizzled)
        #pragma unroll
        for (int nt = 0; nt < 4; nt++) {
            int col = wn * 32 + nt * 8 + p2;
            float bv0 = __ldg(b1g + e * HH + c4 * 64 + col);
            float bv1 = __ldg(b1g + e * HH + c4 * 64 + col + 1);
            int r0 = wm * 16 + q, r1 = r0 + 8;
            float v00 = g * fmaxf(acc1[nt][0] + bv0, 0.f);
            float v01 = g * fmaxf(acc1[nt][1] + bv1, 0.f);
            float v10 = g * fmaxf(acc1[nt][2] + bv0, 0.f);
            float v11 = g * fmaxf(acc1[nt][3] + bv1, 0.f);
            uint32_t o0 = (uint32_t)r0 * 128 + (uint32_t)((((col >> 3) ^ (r0 & 7)) << 4) + ((col * 2) & 15));
            uint32_t o1 = (uint32_t)r1 * 128 + (uint32_t)((((col >> 3) ^ (r1 & 7)) << 4) + ((col * 2) & 15));
            *(__half2*)(smem + SM_H + o0) = __floats2half2_rn(v00, v01);
            *(__half2*)(smem + SM_H + o1) = __floats2half2_rn(v10, v11);
        }

        // ---- GEMM2: 4 k16 subs, rotating buffers ----
        #pragma unroll
        for (int kt = 0; kt < 4; kt++) {
            if (kt == 1) { CP_WAIT(1); } else { CP_WAIT(2); }
            __syncthreads();
            if (kt == 1) {
                load_b2t(sb, gs + 3, e0, e1, tid); CP_COMMIT();
                load_b1t(sb, ch + 1, e0, e1, tid); CP_COMMIT();
            } else if (kt == 2) {
                load_b2t(sb, gs + 4, e0, e1, tid); CP_COMMIT();
            } else if (kt == 3) {
                load_b2t(sb, gs + 5, e0, e1, tid); CP_COMMIT();
            }
            uint32_t bufb = sb + SM_B2 + (uint32_t)((gs + kt) % 3) * B2SZ;
            uint32_t hah[4];
            uint32_t sa = (uint32_t)(((kt * 2 + (t >> 1)) ^ axor) << 4);
            ldsm4(hah, hbase + sa);
            #pragma unroll
            for (int ntp = 0; ntp < 5; ntp++) {
                int rW = rW0 + ntp * 16;
                uint32_t a = bufb + (uint32_t)rW * 32 + (uint32_t)((t & 1) << 4);
                uint32_t bh[4];
                ldsm4(bh, a);
                mma16(acc2[ntp * 2],     hah, bh[0], bh[1]);
                mma16(acc2[ntp * 2 + 1], hah, bh[2], bh[3]);
            }
        }
    }

    // ---- final epilogue: combined bias + store ----
    const float* bc = (const float*)(smem + SM_BIAS);
    int r0 = wm * 16 + q;
    #pragma unroll
    for (int nt = 0; nt < 10; nt++) {
        int col = wn * 80 + nt * 8 + p2;
        float bv0 = bc[col], bv1 = bc[col + 1];
        if (r0 < NTOK) {
            float2 v = make_float2(acc2[nt][0] + bv0, acc2[nt][1] + bv1);
            *(float2*)(out + (b * NTOK + r0) * T2 + col) = v;
        }
        if (r0 + 8 < NTOK) {
            float2 v = make_float2(acc2[nt][2] + bv0, acc2[nt][3] + bv1);
            *(float2*)(out + (b * NTOK + r0 + 8) * T2 + col) = v;
        }
    }
}

extern "C" void kernel_launch(void* const* d_in, const int* in_sizes, int n_in,
                              void* d_out, int out_size) {
    const float* x  = (const float*)d_in[0];
    const float* rw = (const float*)d_in[1];
    const float* rb = (const float*)d_in[2];
    const float* w1 = (const float*)d_in[3];
    const float* b1 = (const float*)d_in[4];
    const float* w2 = (const float*)d_in[5];
    const float* b2 = (const float*)d_in[6];
    float* out = (float*)d_out;

    prep_w<<<dim3(72, 1, EE), dim3(32, 8)>>>(w1, w2);
    router_kernel<<<BB, 128>>>(x, rw, rb);

    cudaFuncSetAttribute(moe_kernel, cudaFuncAttributeMaxDynamicSharedMemorySize, SM_TOT);
    moe_kernel<<<BB, 256, SM_TOT>>>(x, b1, b2, out);
}

// round 11
// speedup vs baseline: 2.1525x; 1.2751x over previous
#include <cuda_runtime.h>
#include <cuda_fp16.h>
#include <cstdint>

#define BB 256
#define NTOK 63
#define DD 128
#define EE 8
#define HH 256
#define T2 160

// ---------------- device globals ----------------
__device__ float g_gates[BB * 2];
__device__ int   g_eidx[BB * 2];
__device__ __half W1T[EE * HH * DD];     // [e][hcol][d] k-contig, fp16
__device__ __half W2T[EE * 4 * T2 * 64]; // [e][kchunk][o][64], fp16

// ---------------- smem layout (bytes) ----------------
#define SM_X   0                      // x: 64 rows x 256B (swz)
#define SM_H   16384                  // h chunk: 64 rows x 128B (swz)
#define SM_B1  24576                  // W1 chunk: 2 bufs x 16384 (swz)
#define SM_B2  57344                  // W2 chunk: 2 bufs x 20480 (160 rows x 128B, swz)
#define B2SZ   20480
#define SM_BIAS 98304                 // 160 floats
#define SM_TOT  99328

// ---------------- PTX helpers ----------------
__device__ __forceinline__ uint32_t smem_u32(const void* p) {
    uint32_t a;
    asm("{ .reg .u64 t; cvta.to.shared.u64 t, %1; cvt.u32.u64 %0, t; }" : "=r"(a) : "l"(p));
    return a;
}
__device__ __forceinline__ void ldsm4(uint32_t* r, uint32_t addr) {
    asm volatile("ldmatrix.sync.aligned.m8n8.x4.shared.b16 {%0,%1,%2,%3}, [%4];"
        : "=r"(r[0]), "=r"(r[1]), "=r"(r[2]), "=r"(r[3]) : "r"(addr));
}
__device__ __forceinline__ void mma16(float* d, const uint32_t* a, uint32_t b0, uint32_t b1) {
    asm volatile("mma.sync.aligned.m16n8k16.row.col.f32.f16.f16.f32 "
        "{%0,%1,%2,%3}, {%4,%5,%6,%7}, {%8,%9}, {%0,%1,%2,%3};"
        : "+f"(d[0]), "+f"(d[1]), "+f"(d[2]), "+f"(d[3])
        : "r"(a[0]), "r"(a[1]), "r"(a[2]), "r"(a[3]), "r"(b0), "r"(b1));
}
__device__ __forceinline__ void cp16(uint32_t dst, const void* src) {
    asm volatile("cp.async.cg.shared.global [%0], [%1], 16;" :: "r"(dst), "l"(src));
}
#define CP_COMMIT() asm volatile("cp.async.commit_group;" ::: "memory")
#define CP_WAIT(n)  asm volatile("cp.async.wait_group %0;" :: "n"(n) : "memory")

// ---------------- prep: transpose + fp16 convert + fused router ----------------
__global__ void prep_w(const float* __restrict__ w1, const float* __restrict__ w2,
                       const float* __restrict__ x,  const float* __restrict__ rw,
                       const float* __restrict__ rb) {
    __shared__ float t[32][33];
    __shared__ float pooled[DD];
    __shared__ float logits[EE];
    int e = blockIdx.z, bx = blockIdx.x;
    int tx = threadIdx.x, ty = threadIdx.y;
    int tid = ty * 32 + tx;
    if (bx < 32) {
        int d0 = (bx & 3) * 32, h0 = (bx >> 2) * 32;
        #pragma unroll
        for (int i = 0; i < 4; i++)
            t[ty + 8 * i][tx] = w1[(e * DD + d0 + ty + 8 * i) * HH + h0 + tx];
        __syncthreads();
        #pragma unroll
        for (int i = 0; i < 4; i++)
            W1T[(e * HH + h0 + ty + 8 * i) * DD + d0 + tx] =
                __float2half_rn(t[tx][ty + 8 * i]);
    } else if (bx < 72) {
        int i2 = bx - 32;
        int k0 = (i2 & 7) * 32, o0 = (i2 >> 3) * 32;
        #pragma unroll
        for (int i = 0; i < 4; i++)
            t[ty + 8 * i][tx] = w2[(e * HH + k0 + ty + 8 * i) * T2 + o0 + tx];
        __syncthreads();
        #pragma unroll
        for (int i = 0; i < 4; i++) {
            int hd = k0 + tx, o = o0 + ty + 8 * i;
            W2T[((e * 4 + (hd >> 6)) * T2 + o) * 64 + (hd & 63)] =
                __float2half_rn(t[tx][ty + 8 * i]);
        }
    } else {
        // router for batch b
        int b = (bx - 72) * 8 + e;
        const float* xb = x + b * 64 * DD;
        if (tid < DD) {
            float s = 0.f;
            #pragma unroll 4
            for (int n = 1; n < 64; n++) s += xb[n * DD + tid];
            pooled[tid] = s * (1.0f / 63.0f);
        }
        __syncthreads();
        if (tid < EE) {
            float l = rb[tid];
            #pragma unroll 4
            for (int dd = 0; dd < DD; dd++) l += pooled[dd] * rw[dd * EE + tid];
            logits[tid] = l;
        }
        __syncthreads();
        if (tid == 0) {
            float mx = logits[0];
            #pragma unroll
            for (int k = 1; k < EE; k++) mx = fmaxf(mx, logits[k]);
            float p[EE];
            float se = 0.f;
            #pragma unroll
            for (int k = 0; k < EE; k++) { p[k] = expf(logits[k] - mx); se += p[k]; }
            int i1 = 0;
            #pragma unroll
            for (int k = 1; k < EE; k++) if (p[k] > p[i1]) i1 = k;
            int i2 = (i1 == 0) ? 1 : 0;
            #pragma unroll
            for (int k = 0; k < EE; k++) if (k != i1 && p[k] > p[i2]) i2 = k;
            float inv = 1.f / se;
            g_eidx[b * 2 + 0]  = i1;
            g_gates[b * 2 + 0] = p[i1] * inv;
            g_eidx[b * 2 + 1]  = i2;
            g_gates[b * 2 + 1] = p[i2] * inv;
        }
    }
}

// ---------------- cp.async tile loaders (over-range calls are empty) ----------------
__device__ __forceinline__ void load_b1t(uint32_t sb, int ch, int e0, int e1, int tid) {
    if (ch >= 8) return;
    int e = (ch >> 2) ? e1 : e0;
    const char* s = (const char*)(W1T + (e * HH + (ch & 3) * 64) * DD);
    uint32_t dst = sb + SM_B1 + (uint32_t)(ch & 1) * 16384;
    #pragma unroll
    for (int i = 0; i < 4; i++) {
        int c = tid + i * 256;
        int row = c >> 4, seg = c & 15;
        uint32_t d = (uint32_t)row * 256 + (uint32_t)((seg ^ (row & 7)) << 4);
        cp16(dst + d, s + c * 16);
    }
}
// full 64-col W2 chunk: 160 rows x 128B, swizzled (8 segs/row)
__device__ __forceinline__ void load_b2t(uint32_t sb, int ch, int e0, int e1, int tid) {
    if (ch >= 8) return;
    int e = (ch >> 2) ? e1 : e0;
    const char* s = (const char*)(W2T + (e * 4 + (ch & 3)) * T2 * 64);
    uint32_t buf = sb + SM_B2 + (uint32_t)(ch & 1) * B2SZ;
    #pragma unroll
    for (int i = 0; i < 5; i++) {
        int c = tid + i * 256;  // 1280 copies
        int row = c >> 3, seg = c & 7;
        uint32_t d = (uint32_t)row * 128 + (uint32_t)((seg ^ (row & 7)) << 4);
        cp16(buf + d, s + row * 128 + seg * 16);
    }
}

// ---------------- main fused kernel: 2 barriers per chunk ----------------
__global__ __launch_bounds__(256, 2) void moe_kernel(
    const float* __restrict__ x,
    const float* __restrict__ b1g,
    const float* __restrict__ b2g,
    float* __restrict__ out) {
    extern __shared__ char smem[];
    uint32_t sb = smem_u32(smem);
    int tid = threadIdx.x, wid = tid >> 5, lane = tid & 31;
    int b = blockIdx.x;
    const int wm = wid & 3, wn = wid >> 2;
    const int t = lane >> 3, r8 = lane & 7, q = lane >> 2, p2 = (lane & 3) * 2;

    const int e0 = g_eidx[b * 2 + 0], e1 = g_eidx[b * 2 + 1];
    const float gt0 = g_gates[b * 2 + 0], gt1 = g_gates[b * 2 + 1];

    if (tid < T2)
        ((float*)(smem + SM_BIAS))[tid] =
            gt0 * __ldg(b2g + e0 * T2 + tid) + gt1 * __ldg(b2g + e1 * T2 + tid);

    // zero x row 63
    if (tid < 16) {
        uint32_t off = 63u * 256 + (uint32_t)((tid ^ 7) << 4);
        *(uint4*)(smem + SM_X + off) = make_uint4(0, 0, 0, 0);
    }
    // fill x rows 0..62, fp16, swizzled
    if (tid < 252) {
        int r = tid >> 2, seg32 = (tid & 3) * 32;
        const float4* xr = (const float4*)(x + (b * 64 + 1 + r) * DD + seg32);
        #pragma unroll
        for (int j = 0; j < 8; j++) {
            float4 v = xr[j];
            int d = seg32 + j * 4;
            __half2 h01 = __floats2half2_rn(v.x, v.y);
            __half2 h23 = __floats2half2_rn(v.z, v.w);
            uint32_t off = (uint32_t)r * 256 + (uint32_t)((((d >> 3) ^ (r & 7)) << 4) + ((d * 2) & 15));
            *(__half2*)(smem + SM_X + off)     = h01;
            *(__half2*)(smem + SM_X + off + 4) = h23;
        }
    }
    __syncthreads();

    // prologue commit order: [B1(0)] [B2(0)] [B1(1)]
    load_b1t(sb, 0, e0, e1, tid);  CP_COMMIT();
    load_b2t(sb, 0, e0, e1, tid);  CP_COMMIT();
    load_b1t(sb, 1, e0, e1, tid);  CP_COMMIT();

    const int rA = wm * 16 + (t & 1) * 8 + r8;
    const uint32_t xbase = sb + SM_X + (uint32_t)rA * 256;
    const uint32_t hbase = sb + SM_H + (uint32_t)rA * 128;
    const int axor = rA & 7;
    const int rB0 = wn * 32 + (t >> 1) * 8 + r8;
    const int rW0 = wn * 80 + (t >> 1) * 8 + r8;

    float acc2[10][4];
    #pragma unroll
    for (int nt = 0; nt < 10; nt++)
        #pragma unroll
        for (int j = 0; j < 4; j++) acc2[nt][j] = 0.f;

    for (int ch = 0; ch < 8; ch++) {
        const int   e  = (ch >> 2) ? e1 : e0;
        const float g  = (ch >> 2) ? gt1 : gt0;
        const int   c4 = ch & 3;

        // ---- sync#1: B1(ch) ready (oldest pending); H free ----
        CP_WAIT(2);
        __syncthreads();

        float acc1[4][4];
        #pragma unroll
        for (int nt = 0; nt < 4; nt++)
            #pragma unroll
            for (int j = 0; j < 4; j++) acc1[nt][j] = 0.f;

        uint32_t b1base = sb + SM_B1 + (uint32_t)(ch & 1) * 16384;
        #pragma unroll
        for (int ks = 0; ks < 8; ks++) {
            uint32_t ah[4];
            uint32_t sa = (uint32_t)(((2 * ks + (t >> 1)) ^ axor) << 4);
            ldsm4(ah, xbase + sa);
            #pragma unroll
            for (int ntp = 0; ntp < 2; ntp++) {
                int rB = rB0 + ntp * 16;
                uint32_t a = b1base + (uint32_t)rB * 256 +
                             (uint32_t)(((2 * ks + (t & 1)) ^ (rB & 7)) << 4);
                uint32_t bh[4];
                ldsm4(bh, a);
                mma16(acc1[ntp * 2],     ah, bh[0], bh[1]);
                mma16(acc1[ntp * 2 + 1], ah, bh[2], bh[3]);
            }
        }
        // h epilogue: bias + relu + gate -> fp16 (swizzled)
        #pragma unroll
        for (int nt = 0; nt < 4; nt++) {
            int col = wn * 32 + nt * 8 + p2;
            float bv0 = __ldg(b1g + e * HH + c4 * 64 + col);
            float bv1 = __ldg(b1g + e * HH + c4 * 64 + col + 1);
            int r0 = wm * 16 + q, r1 = r0 + 8;
            float v00 = g * fmaxf(acc1[nt][0] + bv0, 0.f);
            float v01 = g * fmaxf(acc1[nt][1] + bv1, 0.f);
            float v10 = g * fmaxf(acc1[nt][2] + bv0, 0.f);
            float v11 = g * fmaxf(acc1[nt][3] + bv1, 0.f);
            uint32_t o0 = (uint32_t)r0 * 128 + (uint32_t)((((col >> 3) ^ (r0 & 7)) << 4) + ((col * 2) & 15));
            uint32_t o1 = (uint32_t)r1 * 128 + (uint32_t)((((col >> 3) ^ (r1 & 7)) << 4) + ((col * 2) & 15));
            *(__half2*)(smem + SM_H + o0) = __floats2half2_rn(v00, v01);
            *(__half2*)(smem + SM_H + o1) = __floats2half2_rn(v10, v11);
        }

        // ---- sync#2: B2(ch) ready; H visible; B1 buf(ch&1) free; B2 buf((ch+1)&1) free ----
        CP_WAIT(1);
        __syncthreads();
        load_b2t(sb, ch + 1, e0, e1, tid); CP_COMMIT();
        load_b1t(sb, ch + 2, e0, e1, tid); CP_COMMIT();

        // ---- GEMM2: full 64-k chunk, no intermediate barriers ----
        uint32_t b2base = sb + SM_B2 + (uint32_t)(ch & 1) * B2SZ;
        #pragma unroll
        for (int kt = 0; kt < 4; kt++) {
            uint32_t hah[4];
            uint32_t sa = (uint32_t)(((kt * 2 + (t >> 1)) ^ axor) << 4);
            ldsm4(hah, hbase + sa);
            #pragma unroll
            for (int ntp = 0; ntp < 5; ntp++) {
                int rW = rW0 + ntp * 16;
                uint32_t a = b2base + (uint32_t)rW * 128 +
                             (uint32_t)(((kt * 2 + (t & 1)) ^ (rW & 7)) << 4);
                uint32_t bh[4];
                ldsm4(bh, a);
                mma16(acc2[ntp * 2],     hah, bh[0], bh[1]);
                mma16(acc2[ntp * 2 + 1], hah, bh[2], bh[3]);
            }
        }
    }

    // ---- final epilogue: combined bias + store ----
    const float* bc = (const float*)(smem + SM_BIAS);
    int r0 = wm * 16 + q;
    #pragma unroll
    for (int nt = 0; nt < 10; nt++) {
        int col = wn * 80 + nt * 8 + p2;
        float bv0 = bc[col], bv1 = bc[col + 1];
        if (r0 < NTOK) {
            float2 v = make_float2(acc2[nt][0] + bv0, acc2[nt][1] + bv1);
            *(float2*)(out + (b * NTOK + r0) * T2 + col) = v;
        }
        if (r0 + 8 < NTOK) {
            float2 v = make_float2(acc2[nt][2] + bv0, acc2[nt][3] + bv1);
            *(float2*)(out + (b * NTOK + r0 + 8) * T2 + col) = v;
        }
    }
}

extern "C" void kernel_launch(void* const* d_in, const int* in_sizes, int n_in,
                              void* d_out, int out_size) {
    const float* x  = (const float*)d_in[0];
    const float* rw = (const float*)d_in[1];
    const float* rb = (const float*)d_in[2];
    const float* w1 = (const float*)d_in[3];
    const float* b1 = (const float*)d_in[4];
    const float* w2 = (const float*)d_in[5];
    const float* b2 = (const float*)d_in[6];
    float* out = (float*)d_out;

    prep_w<<<dim3(104, 1, EE), dim3(32, 8)>>>(w1, w2, x, rw, rb);

    cudaFuncSetAttribute(moe_kernel, cudaFuncAttributeMaxDynamicSharedMemorySize, SM_TOT);
    moe_kernel<<<BB, 256, SM_TOT>>>(x, b1, b2, out);
}